// round 7
// baseline (speedup 1.0000x reference)
#include <cuda_runtime.h>
#include <cuda_bf16.h>
#include <cstdint>
#include <cstddef>

// Node2GraphAttention:
//   coef[i] = sigmoid( dot(n_emb[i], g_emb[batch[i]]) )
//   out[g]  = sum_{i: batch[i]==g} coef[i] * n_emb[i]
// n_batch SORTED. Block-cooperative TMA-bulk pipeline:
//   - block owns a contiguous node span; 16-node (8KB) stages loaded with ONE
//     cp.async.bulk into a 2-deep SMEM ring (mbarrier full/empty) -> deep
//     outstanding-byte window through the TMA path (bypasses L1 MSHR cap)
//   - 4 warps x 4 nodes per stage; per-warp node subsequence stays monotone,
//     so segment-register accumulation + cached g-row still work
//   - red.global.add.v4.f32 only at segment boundaries / span edges

#define D 128
#define D4 (D / 4)                    // 32 float4 per row
#define NPS 16                        // nodes per stage
#define STAGE_BYTES (NPS * D * 4)     // 8192
#define STAGES 2
#define THREADS 128
#define MIN_BLOCKS 12

typedef unsigned long long mbar_t;

__device__ int g_idx_is64;            // 1 if n_batch is int64, 0 if int32

// Zero output AND detect index dtype (2 launches/call so ncu -s 5 -c 1
// captures the MAIN kernel). Sorted values in [0,G): reinterpreted as int32,
// element N-1 is a zero high word iff the data is little-endian int64.
__global__ void init_kernel(float* __restrict__ out, int n,
                            const int* __restrict__ nb32, int N) {
    int i = blockIdx.x * blockDim.x + threadIdx.x;
    if (i < n) out[i] = 0.0f;
    if (i == 0) g_idx_is64 = (nb32[N - 1] == 0) ? 1 : 0;
}

__device__ __forceinline__ int load_batch(const void* __restrict__ nb, int i, int is64) {
    if (is64) return (int)(((const long long*)nb)[i]);
    return ((const int*)nb)[i];
}

__device__ __forceinline__ float sigmoidf_(float x) {
    return 1.0f / (1.0f + __expf(-x));
}

__device__ __forceinline__ float dot4(const float4& a, const float4& b) {
    return a.x * b.x + a.y * b.y + a.z * b.z + a.w * b.w;
}

__device__ __forceinline__ void flush_seg(float* __restrict__ out, int b, int lane,
                                          const float4& acc) {
    float* p = out + b * D + lane * 4;   // 16B aligned
    asm volatile("red.global.add.v4.f32 [%0], {%1, %2, %3, %4};"
                 :: "l"(p), "f"(acc.x), "f"(acc.y), "f"(acc.z), "f"(acc.w)
                 : "memory");
}

__device__ __forceinline__ void acc_add(float4& acc, float c, const float4& nv) {
    acc.x += c * nv.x;
    acc.y += c * nv.y;
    acc.z += c * nv.z;
    acc.w += c * nv.w;
}

// ---- mbarrier / bulk-copy helpers ----
__device__ __forceinline__ unsigned s2u(const void* p) {
    return (unsigned)__cvta_generic_to_shared(p);
}
__device__ __forceinline__ void mbar_init(mbar_t* m, unsigned cnt) {
    asm volatile("mbarrier.init.shared.b64 [%0], %1;" :: "r"(s2u(m)), "r"(cnt) : "memory");
}
__device__ __forceinline__ void mbar_arrive(mbar_t* m) {
    asm volatile("mbarrier.arrive.shared.b64 _, [%0];" :: "r"(s2u(m)) : "memory");
}
__device__ __forceinline__ void mbar_expect_tx(mbar_t* m, unsigned bytes) {
    asm volatile("mbarrier.arrive.expect_tx.shared.b64 _, [%0], %1;"
                 :: "r"(s2u(m)), "r"(bytes) : "memory");
}
__device__ __forceinline__ void mbar_wait(mbar_t* m, unsigned phase) {
    unsigned a = s2u(m);
    asm volatile(
        "{\n\t"
        ".reg .pred P;\n\t"
        "WAIT_%=:\n\t"
        "mbarrier.try_wait.parity.acquire.cta.shared::cta.b64 P, [%0], %1, 0x989680;\n\t"
        "@P bra.uni DONE_%=;\n\t"
        "bra.uni WAIT_%=;\n\t"
        "DONE_%=:\n\t"
        "}"
        :: "r"(a), "r"(phase) : "memory");
}
__device__ __forceinline__ void bulk_g2s(void* smem_dst, const void* __restrict__ gsrc,
                                         mbar_t* mbar) {
    asm volatile("cp.async.bulk.shared::cta.global.mbarrier::complete_tx::bytes "
                 "[%0], [%1], %2, [%3];"
                 :: "r"(s2u(smem_dst)), "l"(gsrc), "r"((unsigned)STAGE_BYTES),
                    "r"(s2u(mbar)) : "memory");
}

// Fused butterfly reduction of 4 per-lane partials -> 4 warp sums,
// sigmoid applied once, then broadcast. 13 SHFL + 1 MUFU per 4 nodes.
__device__ __forceinline__ void reduce4_sigmoid(float d0, float d1, float d2, float d3,
                                                float& c0, float& c1, float& c2, float& c3,
                                                int lane) {
    const unsigned m = 0xffffffffu;
    float t0 = __shfl_xor_sync(m, d0, 16);
    float t1 = __shfl_xor_sync(m, d1, 16);
    float t2 = __shfl_xor_sync(m, d2, 16);
    float t3 = __shfl_xor_sync(m, d3, 16);
    bool hi16 = (lane & 16) != 0;
    float a = hi16 ? (d2 + t2) : (d0 + t0);
    float b = hi16 ? (d3 + t3) : (d1 + t1);
    float ta = __shfl_xor_sync(m, a, 8);
    float tb = __shfl_xor_sync(m, b, 8);
    bool hi8 = (lane & 8) != 0;
    float c = hi8 ? (b + tb) : (a + ta);
    c += __shfl_xor_sync(m, c, 4);
    c += __shfl_xor_sync(m, c, 2);
    c += __shfl_xor_sync(m, c, 1);
    float s = sigmoidf_(c);
    c0 = __shfl_sync(m, s, 0);
    c1 = __shfl_sync(m, s, 8);
    c2 = __shfl_sync(m, s, 16);
    c3 = __shfl_sync(m, s, 24);
}

__global__ void __launch_bounds__(THREADS, MIN_BLOCKS)
n2g_attention_kernel(const float4* __restrict__ n4,
                     const float4* __restrict__ g4,
                     const void*  __restrict__ nb,
                     float* __restrict__ out,
                     int N, int span) {
    __shared__ __align__(128) float4 sbuf[STAGES][NPS][32];   // 2 x 8KB
    __shared__ mbar_t mb_full[STAGES];
    __shared__ mbar_t mb_empty[STAGES];

    const int tid  = threadIdx.x;
    const int lane = tid & 31;
    const int w    = tid >> 5;

    const int blk_start = blockIdx.x * span;
    if (blk_start >= N) return;
    int blk_end = blk_start + span;
    if (blk_end > N) blk_end = N;
    const int cnt        = blk_end - blk_start;
    const int nstages    = cnt >> 4;                 // full 16-node stages
    const int tail_start = blk_start + (nstages << 4);
    const int is64       = g_idx_is64;

    if (tid == 0) {
        #pragma unroll
        for (int s = 0; s < STAGES; ++s) {
            mbar_init(&mb_full[s], 1);
            mbar_init(&mb_empty[s], THREADS);
        }
    }
    __syncthreads();

    // producer prologue: fill the ring
    if (tid == 0) {
        const int pre = nstages < STAGES ? nstages : STAGES;
        for (int s = 0; s < pre; ++s) {
            mbar_expect_tx(&mb_full[s], STAGE_BYTES);
            bulk_g2s(&sbuf[s][0][0], &n4[(size_t)(blk_start + s * NPS) * D4], &mb_full[s]);
        }
    }

    // warp's first node (stage path owns blk_start + w*4; else tail chunk)
    int my_first;
    if (nstages > 0) {
        my_first = blk_start + (w << 2);
    } else {
        const int t = tail_start + (w << 2);
        my_first = (t < blk_end) ? t : -1;
    }

    float4 acc = make_float4(0.f, 0.f, 0.f, 0.f);
    int    cur_b = 0;
    float4 gv = make_float4(0.f, 0.f, 0.f, 0.f);
    if (my_first >= 0) {
        cur_b = load_batch(nb, my_first, is64);
        gv = __ldg(&g4[cur_b * D4 + lane]);
    }

    for (int k = 0; k < nstages; ++k) {
        const int buf = k & 1;
        const int ph  = (k >> 1) & 1;
        mbar_wait(&mb_full[buf], ph);

        const int base = blk_start + (k << 4) + (w << 2);
        const int slot = w << 2;
        const int b3 = load_batch(nb, base + 3, is64);

        if (b3 == cur_b) {
            // fast path: whole group inside current segment (avg seg = 50)
            const float d0 = dot4(sbuf[buf][slot + 0][lane], gv);
            const float d1 = dot4(sbuf[buf][slot + 1][lane], gv);
            const float d2 = dot4(sbuf[buf][slot + 2][lane], gv);
            const float d3 = dot4(sbuf[buf][slot + 3][lane], gv);
            float c0, c1, c2, c3;
            reduce4_sigmoid(d0, d1, d2, d3, c0, c1, c2, c3, lane);
            acc_add(acc, c0, sbuf[buf][slot + 0][lane]);
            acc_add(acc, c1, sbuf[buf][slot + 1][lane]);
            acc_add(acc, c2, sbuf[buf][slot + 2][lane]);
            acc_add(acc, c3, sbuf[buf][slot + 3][lane]);
        } else {
            // slow path: segment boundary inside this group
            #pragma unroll
            for (int j = 0; j < 4; ++j) {
                const int b = (j == 3) ? b3 : load_batch(nb, base + j, is64);
                if (b != cur_b) {
                    flush_seg(out, cur_b, lane, acc);
                    acc = make_float4(0.f, 0.f, 0.f, 0.f);
                    cur_b = b;
                    gv = __ldg(&g4[b * D4 + lane]);
                }
                const float4 nv = sbuf[buf][slot + j][lane];
                float d = dot4(nv, gv);
                #pragma unroll
                for (int o = 16; o > 0; o >>= 1)
                    d += __shfl_xor_sync(0xffffffffu, d, o);
                acc_add(acc, sigmoidf_(d), nv);
            }
        }

        mbar_arrive(&mb_empty[buf]);      // all 128 threads release the buffer

        if (tid == 0 && k + STAGES < nstages) {
            mbar_wait(&mb_empty[buf], ph);                 // stage-k drain done
            asm volatile("fence.proxy.async.shared::cta;" ::: "memory");
            mbar_expect_tx(&mb_full[buf], STAGE_BYTES);
            bulk_g2s(&sbuf[buf][0][0],
                     &n4[(size_t)(blk_start + (k + STAGES) * NPS) * D4],
                     &mb_full[buf]);
        }
    }

    // scalar tail (< 16 nodes, last working block only)
    if (my_first >= 0) {
        const int t0 = tail_start + (w << 2);
        int t1 = t0 + 4;
        if (t1 > blk_end) t1 = blk_end;
        for (int i = t0; i < t1; ++i) {
            const int b = load_batch(nb, i, is64);
            if (b != cur_b) {
                flush_seg(out, cur_b, lane, acc);
                acc = make_float4(0.f, 0.f, 0.f, 0.f);
                cur_b = b;
                gv = __ldg(&g4[b * D4 + lane]);
            }
            const float4 nv = __ldcs(&n4[(size_t)i * D4 + lane]);
            float d = dot4(nv, gv);
            #pragma unroll
            for (int o = 16; o > 0; o >>= 1)
                d += __shfl_xor_sync(0xffffffffu, d, o);
            acc_add(acc, sigmoidf_(d), nv);
        }
        flush_seg(out, cur_b, lane, acc);
    }
}

extern "C" void kernel_launch(void* const* d_in, const int* in_sizes, int n_in,
                              void* d_out, int out_size) {
    const float4* n4 = (const float4*)d_in[0];   // n_embedding [N,128] f32
    const float4* g4 = (const float4*)d_in[1];   // g_embedding [G,128] f32
    const void*   nb = d_in[2];                  // n_batch [N] int32 or int64
    float* out = (float*)d_out;                  // [G,128] f32

    const int N = in_sizes[0] / D;

    init_kernel<<<(out_size + 255) / 256, 256>>>(out, out_size, (const int*)nb, N);

    int sms = 148;
    cudaDeviceGetAttribute(&sms, cudaDevAttrMultiProcessorCount, 0);

    const int target_blocks = sms * MIN_BLOCKS;
    int span = (N + target_blocks - 1) / target_blocks;
    span = (span + NPS - 1) & ~(NPS - 1);        // multiple of 16 nodes
    const int blocks = (N + span - 1) / span;

    n2g_attention_kernel<<<blocks, THREADS>>>(n4, g4, nb, out, N, span);
}

// round 9
// speedup vs baseline: 1.1463x; 1.1463x over previous
#include <cuda_runtime.h>
#include <cuda_bf16.h>
#include <cstdint>
#include <cstddef>

// Node2GraphAttention:
//   coef[i] = sigmoid( dot(n_emb[i], g_emb[batch[i]]) )
//   out[g]  = sum_{i: batch[i]==g} coef[i] * n_emb[i]
// n_batch SORTED (avg segment = 50 nodes):
//   - warp-local register accumulation per segment, red.global.add.v4.f32
//     only at segment boundaries / span edges
//   - g row CACHED in registers (reload on segment change), L2 evict-last
//     via createpolicy + ld.global.nc.L2::cache_hint
//   - n rows staged through SMEM via cp.async with L2 evict-first
//     (barrier-free: each lane consumes only the 16B it copied)
//   - balanced persistent grid: every warp owns one contiguous span

#define D 128
#define D4 (D / 4)            // 32 float4 per row -> one float4 per lane
#define GROUP 4               // nodes per pipeline group
#define STAGES 2              // smem double buffer
#define THREADS 128
#define WARPS_PER_BLOCK (THREADS / 32)
#define MIN_BLOCKS 13         // push reg budget to <=39 -> 52 warps/SM

__device__ int g_idx_is64;    // 1 if n_batch is int64, 0 if int32

// Zero output (vectorized) AND detect index dtype (2 launches per call so
// ncu -s 5 -c 1 captures the MAIN kernel).
// Detection: values in [0,G) sorted ascending; reinterpreted as int32,
// element N-1 is a zero high word iff data is little-endian int64.
__global__ void init_kernel(float4* __restrict__ out4, int n4cnt,
                            const int* __restrict__ nb32, int N) {
    int i = blockIdx.x * blockDim.x + threadIdx.x;
    if (i < n4cnt) out4[i] = make_float4(0.f, 0.f, 0.f, 0.f);
    if (i == 0) g_idx_is64 = (nb32[N - 1] == 0) ? 1 : 0;
}

__device__ __forceinline__ int load_batch(const void* __restrict__ nb, int i, int is64) {
    if (is64) return (int)(((const long long*)nb)[i]);
    return ((const int*)nb)[i];
}

__device__ __forceinline__ float sigmoidf_(float x) {
    return 1.0f / (1.0f + __expf(-x));
}

__device__ __forceinline__ float dot4(const float4& a, const float4& b) {
    return a.x * b.x + a.y * b.y + a.z * b.z + a.w * b.w;
}

// One vector reduction instruction per lane (sm_90+), no return value.
__device__ __forceinline__ void flush_seg(float* __restrict__ out, int b, int lane,
                                          const float4& acc) {
    float* p = out + b * D + lane * 4;   // 16B aligned
    asm volatile("red.global.add.v4.f32 [%0], {%1, %2, %3, %4};"
                 :: "l"(p), "f"(acc.x), "f"(acc.y), "f"(acc.z), "f"(acc.w)
                 : "memory");
}

__device__ __forceinline__ void acc_add(float4& acc, float c, const float4& nv) {
    acc.x += c * nv.x;
    acc.y += c * nv.y;
    acc.z += c * nv.z;
    acc.w += c * nv.w;
}

// ---- L2 policy helpers (cache_hint form: portable across ptxas builds) ----
__device__ __forceinline__ unsigned long long mk_policy_ef() {
    unsigned long long pol;
    asm volatile("createpolicy.fractional.L2::evict_first.b64 %0, 1.0;" : "=l"(pol));
    return pol;
}
__device__ __forceinline__ unsigned long long mk_policy_el() {
    unsigned long long pol;
    asm volatile("createpolicy.fractional.L2::evict_last.b64 %0, 1.0;" : "=l"(pol));
    return pol;
}

// g-row load with L2 evict-last hint (keep the hot 5MB table resident).
__device__ __forceinline__ float4 load_g(const float4* __restrict__ p,
                                         unsigned long long pol) {
    float4 v;
    asm volatile("ld.global.nc.L2::cache_hint.v4.f32 {%0, %1, %2, %3}, [%4], %5;"
                 : "=f"(v.x), "=f"(v.y), "=f"(v.z), "=f"(v.w)
                 : "l"(p), "l"(pol));
    return v;
}

// n-stream cp.async with L2 evict-first (use-once data must not thrash L2).
__device__ __forceinline__ void cp16_ef(float4* dst_smem, const float4* __restrict__ src,
                                        unsigned long long pol) {
    unsigned saddr = (unsigned)__cvta_generic_to_shared(dst_smem);
    asm volatile("cp.async.cg.shared.global.L2::cache_hint [%0], [%1], 16, %2;"
                 :: "r"(saddr), "l"(src), "l"(pol) : "memory");
}
#define CP_COMMIT()  asm volatile("cp.async.commit_group;" ::: "memory")
#define CP_WAIT1()   asm volatile("cp.async.wait_group 1;" ::: "memory")
#define CP_WAIT0()   asm volatile("cp.async.wait_group 0;" ::: "memory")

// Fused butterfly reduction of 4 per-lane partials -> 4 warp sums,
// sigmoid applied once (4 nodes share one MUFU), then broadcast.
// 13 SHFL + 1 MUFU per 4 nodes.
__device__ __forceinline__ void reduce4_sigmoid(float d0, float d1, float d2, float d3,
                                                float& c0, float& c1, float& c2, float& c3,
                                                int lane) {
    const unsigned m = 0xffffffffu;
    float t0 = __shfl_xor_sync(m, d0, 16);
    float t1 = __shfl_xor_sync(m, d1, 16);
    float t2 = __shfl_xor_sync(m, d2, 16);
    float t3 = __shfl_xor_sync(m, d3, 16);
    bool hi16 = (lane & 16) != 0;
    float a = hi16 ? (d2 + t2) : (d0 + t0);
    float b = hi16 ? (d3 + t3) : (d1 + t1);
    float ta = __shfl_xor_sync(m, a, 8);
    float tb = __shfl_xor_sync(m, b, 8);
    bool hi8 = (lane & 8) != 0;
    float c = hi8 ? (b + tb) : (a + ta);
    c += __shfl_xor_sync(m, c, 4);
    c += __shfl_xor_sync(m, c, 2);
    c += __shfl_xor_sync(m, c, 1);
    float s = sigmoidf_(c);
    c0 = __shfl_sync(m, s, 0);
    c1 = __shfl_sync(m, s, 8);
    c2 = __shfl_sync(m, s, 16);
    c3 = __shfl_sync(m, s, 24);
}

__global__ void __launch_bounds__(THREADS, MIN_BLOCKS)
n2g_attention_kernel(const float4* __restrict__ n4,
                     const float4* __restrict__ g4,
                     const void*  __restrict__ nb,
                     float* __restrict__ out,
                     int N, int span) {
    __shared__ float4 sbuf[WARPS_PER_BLOCK][STAGES][GROUP][32];

    const int lane  = threadIdx.x & 31;
    const int w     = threadIdx.x >> 5;
    const int wglob = blockIdx.x * WARPS_PER_BLOCK + w;

    int start = wglob * span;
    if (start >= N) return;
    int end = start + span;
    if (end > N) end = N;

    const int is64 = g_idx_is64;
    const unsigned long long pol_ef = mk_policy_ef();
    const unsigned long long pol_el = mk_policy_el();

    float4 acc = make_float4(0.f, 0.f, 0.f, 0.f);
    int    cur_b = load_batch(nb, start, is64);
    float4 gv    = load_g(&g4[cur_b * D4 + lane], pol_el);   // cached graph row

    const int cnt     = end - start;
    const int ngroups = cnt >> 2;        // full groups of 4
    int i = start;

    if (ngroups >= STAGES) {
        // prologue: prefetch groups 0,1
        #pragma unroll
        for (int s = 0; s < STAGES; ++s) {
            #pragma unroll
            for (int j = 0; j < GROUP; ++j)
                cp16_ef(&sbuf[w][s][j][lane], &n4[(start + s * GROUP + j) * D4 + lane], pol_ef);
            CP_COMMIT();
        }

        for (int k = 0; k < ngroups; ++k) {
            const int s    = k & 1;
            const int base = start + (k << 2);

            // monotone indices: if last node of group matches cur_b,
            // the whole group is in the current segment.
            const int b3 = load_batch(nb, base + 3, is64);

            CP_WAIT1();   // group k resident (all prior groups complete)

            if (b3 == cur_b) {
                // ---- fast path: cached gv, no flush checks ----
                const float d0 = dot4(sbuf[w][s][0][lane], gv);
                const float d1 = dot4(sbuf[w][s][1][lane], gv);
                const float d2 = dot4(sbuf[w][s][2][lane], gv);
                const float d3 = dot4(sbuf[w][s][3][lane], gv);

                float c0, c1, c2, c3;
                reduce4_sigmoid(d0, d1, d2, d3, c0, c1, c2, c3, lane);

                acc_add(acc, c0, sbuf[w][s][0][lane]);
                acc_add(acc, c1, sbuf[w][s][1][lane]);
                acc_add(acc, c2, sbuf[w][s][2][lane]);
                acc_add(acc, c3, sbuf[w][s][3][lane]);
            } else {
                // ---- slow path: segment boundary inside this group ----
                #pragma unroll
                for (int j = 0; j < GROUP; ++j) {
                    const int b = (j == 3) ? b3 : load_batch(nb, base + j, is64);
                    if (b != cur_b) {
                        flush_seg(out, cur_b, lane, acc);
                        acc = make_float4(0.f, 0.f, 0.f, 0.f);
                        cur_b = b;
                        gv = load_g(&g4[b * D4 + lane], pol_el);
                    }
                    const float4 nv = sbuf[w][s][j][lane];
                    float d = dot4(nv, gv);
                    #pragma unroll
                    for (int o = 16; o > 0; o >>= 1)
                        d += __shfl_xor_sync(0xffffffffu, d, o);
                    acc_add(acc, sigmoidf_(d), nv);
                }
            }

            // prefetch group k+2 into the buffer we just drained
            if (k + 2 < ngroups) {
                const int nbase = start + ((k + 2) << 2);
                #pragma unroll
                for (int j = 0; j < GROUP; ++j)
                    cp16_ef(&sbuf[w][s][j][lane], &n4[(nbase + j) * D4 + lane], pol_ef);
            }
            CP_COMMIT();  // one commit per iter (possibly empty) keeps wait positional
        }
        CP_WAIT0();
        i = start + (ngroups << 2);
    }

    // scalar tail (also the whole range when ngroups < STAGES)
    for (; i < end; ++i) {
        const int b = load_batch(nb, i, is64);
        if (b != cur_b) {
            flush_seg(out, cur_b, lane, acc);
            acc = make_float4(0.f, 0.f, 0.f, 0.f);
            cur_b = b;
            gv = load_g(&g4[b * D4 + lane], pol_el);
        }
        const float4 nv = __ldcs(&n4[i * D4 + lane]);
        float d = dot4(nv, gv);
        #pragma unroll
        for (int o = 16; o > 0; o >>= 1)
            d += __shfl_xor_sync(0xffffffffu, d, o);
        acc_add(acc, sigmoidf_(d), nv);
    }

    flush_seg(out, cur_b, lane, acc);
}

extern "C" void kernel_launch(void* const* d_in, const int* in_sizes, int n_in,
                              void* d_out, int out_size) {
    const float4* n4 = (const float4*)d_in[0];   // n_embedding [N,128] f32
    const float4* g4 = (const float4*)d_in[1];   // g_embedding [G,128] f32
    const void*   nb = d_in[2];                  // n_batch [N] int32 or int64
    float* out = (float*)d_out;                  // [G,128] f32

    const int N = in_sizes[0] / D;

    const int n4cnt = out_size / 4;              // out_size divisible by D=128
    init_kernel<<<(n4cnt + 255) / 256, 256>>>((float4*)out, n4cnt, (const int*)nb, N);

    int sms = 148;
    cudaDeviceGetAttribute(&sms, cudaDevAttrMultiProcessorCount, 0);

    // balanced persistent grid: every warp gets one contiguous span
    const int blocks      = sms * MIN_BLOCKS;
    const int total_warps = blocks * WARPS_PER_BLOCK;
    int span = (N + total_warps - 1) / total_warps;
    span = (span + GROUP - 1) & ~(GROUP - 1);    // multiple of 4

    n2g_attention_kernel<<<blocks, THREADS>>>(n4, g4, nb, out, N, span);
}

// round 10
// speedup vs baseline: 1.2480x; 1.0887x over previous
#include <cuda_runtime.h>
#include <cuda_bf16.h>
#include <cstdint>
#include <cstddef>

// Node2GraphAttention:
//   coef[i] = sigmoid( dot(n_emb[i], g_emb[batch[i]]) )
//   out[g]  = sum_{i: batch[i]==g} coef[i] * n_emb[i]
// n_batch SORTED (avg segment = 50 nodes):
//   - warp-local register accumulation per segment, red.global.add.v4.f32
//     only at segment boundaries / span edges
//   - g row CACHED in registers, reloaded only on segment change
//   - n rows staged through SMEM via cp.async, 3-deep ring with wait_group 2
//     -> TWO groups (4KB/warp) in flight at all times (deeper per-warp MLP)
//   - barrier-free: each lane consumes only the 16B it copied
//   - balanced persistent grid: every warp owns one contiguous span

#define D 128
#define D4 (D / 4)            // 32 float4 per row -> one float4 per lane
#define GROUP 4               // nodes per pipeline group
#define STAGES 3              // smem triple buffer (2 groups in flight)
#define THREADS 128
#define WARPS_PER_BLOCK (THREADS / 32)
#define MIN_BLOCKS 9          // 9 x 24KB smem = 216KB/SM; regs free (no spills)

__device__ int g_idx_is64;    // 1 if n_batch is int64, 0 if int32

// Zero output (vectorized) AND detect index dtype (2 launches per call so
// ncu -s 5 -c 1 captures the MAIN kernel).
// Detection: values in [0,G) sorted ascending; reinterpreted as int32,
// element N-1 is a zero high word iff data is little-endian int64.
__global__ void init_kernel(float4* __restrict__ out4, int n4cnt,
                            const int* __restrict__ nb32, int N) {
    int i = blockIdx.x * blockDim.x + threadIdx.x;
    if (i < n4cnt) out4[i] = make_float4(0.f, 0.f, 0.f, 0.f);
    if (i == 0) g_idx_is64 = (nb32[N - 1] == 0) ? 1 : 0;
}

__device__ __forceinline__ int load_batch(const void* __restrict__ nb, int i, int is64) {
    if (is64) return (int)(((const long long*)nb)[i]);
    return ((const int*)nb)[i];
}

__device__ __forceinline__ float sigmoidf_(float x) {
    return 1.0f / (1.0f + __expf(-x));
}

__device__ __forceinline__ float dot4(const float4& a, const float4& b) {
    return a.x * b.x + a.y * b.y + a.z * b.z + a.w * b.w;
}

// One vector reduction instruction per lane (sm_90+), no return value.
__device__ __forceinline__ void flush_seg(float* __restrict__ out, int b, int lane,
                                          const float4& acc) {
    float* p = out + b * D + lane * 4;   // 16B aligned
    asm volatile("red.global.add.v4.f32 [%0], {%1, %2, %3, %4};"
                 :: "l"(p), "f"(acc.x), "f"(acc.y), "f"(acc.z), "f"(acc.w)
                 : "memory");
}

__device__ __forceinline__ void acc_add(float4& acc, float c, const float4& nv) {
    acc.x += c * nv.x;
    acc.y += c * nv.y;
    acc.z += c * nv.z;
    acc.w += c * nv.w;
}

__device__ __forceinline__ void cp16(float4* dst_smem, const float4* __restrict__ src) {
    unsigned saddr = (unsigned)__cvta_generic_to_shared(dst_smem);
    asm volatile("cp.async.cg.shared.global [%0], [%1], 16;"
                 :: "r"(saddr), "l"(src) : "memory");
}
#define CP_COMMIT()  asm volatile("cp.async.commit_group;" ::: "memory")
#define CP_WAIT2()   asm volatile("cp.async.wait_group 2;" ::: "memory")
#define CP_WAIT0()   asm volatile("cp.async.wait_group 0;" ::: "memory")

// Fused butterfly reduction of 4 per-lane partials -> 4 warp sums,
// sigmoid applied once (4 nodes share one MUFU), then broadcast.
// 13 SHFL + 1 MUFU per 4 nodes.
__device__ __forceinline__ void reduce4_sigmoid(float d0, float d1, float d2, float d3,
                                                float& c0, float& c1, float& c2, float& c3,
                                                int lane) {
    const unsigned m = 0xffffffffu;
    float t0 = __shfl_xor_sync(m, d0, 16);
    float t1 = __shfl_xor_sync(m, d1, 16);
    float t2 = __shfl_xor_sync(m, d2, 16);
    float t3 = __shfl_xor_sync(m, d3, 16);
    bool hi16 = (lane & 16) != 0;
    float a = hi16 ? (d2 + t2) : (d0 + t0);
    float b = hi16 ? (d3 + t3) : (d1 + t1);
    float ta = __shfl_xor_sync(m, a, 8);
    float tb = __shfl_xor_sync(m, b, 8);
    bool hi8 = (lane & 8) != 0;
    float c = hi8 ? (b + tb) : (a + ta);
    c += __shfl_xor_sync(m, c, 4);
    c += __shfl_xor_sync(m, c, 2);
    c += __shfl_xor_sync(m, c, 1);
    float s = sigmoidf_(c);
    c0 = __shfl_sync(m, s, 0);
    c1 = __shfl_sync(m, s, 8);
    c2 = __shfl_sync(m, s, 16);
    c3 = __shfl_sync(m, s, 24);
}

__global__ void __launch_bounds__(THREADS, MIN_BLOCKS)
n2g_attention_kernel(const float4* __restrict__ n4,
                     const float4* __restrict__ g4,
                     const void*  __restrict__ nb,
                     float* __restrict__ out,
                     int N, int span) {
    __shared__ float4 sbuf[WARPS_PER_BLOCK][STAGES][GROUP][32];   // 24KB

    const int lane  = threadIdx.x & 31;
    const int w     = threadIdx.x >> 5;
    const int wglob = blockIdx.x * WARPS_PER_BLOCK + w;

    int start = wglob * span;
    if (start >= N) return;
    int end = start + span;
    if (end > N) end = N;

    const int is64 = g_idx_is64;

    float4 acc = make_float4(0.f, 0.f, 0.f, 0.f);
    int    cur_b = load_batch(nb, start, is64);
    float4 gv    = __ldg(&g4[cur_b * D4 + lane]);   // cached graph row

    const int cnt     = end - start;
    const int ngroups = cnt >> 2;        // full groups of 4
    int i = start;

    if (ngroups >= STAGES) {
        // prologue: prefetch groups 0..STAGES-1
        #pragma unroll
        for (int s = 0; s < STAGES; ++s) {
            #pragma unroll
            for (int j = 0; j < GROUP; ++j)
                cp16(&sbuf[w][s][j][lane], &n4[(start + s * GROUP + j) * D4 + lane]);
            CP_COMMIT();
        }

        int s = 0;                        // ring slot of group k
        for (int k = 0; k < ngroups; ++k) {
            const int base = start + (k << 2);

            // monotone indices: if last node of group matches cur_b,
            // the whole group is in the current segment.
            const int b3 = load_batch(nb, base + 3, is64);

            CP_WAIT2();   // group k resident; k+1, k+2 still flying

            if (b3 == cur_b) {
                // ---- fast path: cached gv, no flush checks ----
                const float d0 = dot4(sbuf[w][s][0][lane], gv);
                const float d1 = dot4(sbuf[w][s][1][lane], gv);
                const float d2 = dot4(sbuf[w][s][2][lane], gv);
                const float d3 = dot4(sbuf[w][s][3][lane], gv);

                float c0, c1, c2, c3;
                reduce4_sigmoid(d0, d1, d2, d3, c0, c1, c2, c3, lane);

                acc_add(acc, c0, sbuf[w][s][0][lane]);
                acc_add(acc, c1, sbuf[w][s][1][lane]);
                acc_add(acc, c2, sbuf[w][s][2][lane]);
                acc_add(acc, c3, sbuf[w][s][3][lane]);
            } else {
                // ---- slow path: segment boundary inside this group ----
                #pragma unroll
                for (int j = 0; j < GROUP; ++j) {
                    const int b = (j == 3) ? b3 : load_batch(nb, base + j, is64);
                    if (b != cur_b) {
                        flush_seg(out, cur_b, lane, acc);
                        acc = make_float4(0.f, 0.f, 0.f, 0.f);
                        cur_b = b;
                        gv = __ldg(&g4[b * D4 + lane]);
                    }
                    const float4 nv = sbuf[w][s][j][lane];
                    float d = dot4(nv, gv);
                    #pragma unroll
                    for (int o = 16; o > 0; o >>= 1)
                        d += __shfl_xor_sync(0xffffffffu, d, o);
                    acc_add(acc, sigmoidf_(d), nv);
                }
            }

            // prefetch group k+STAGES into the slot we just drained
            if (k + STAGES < ngroups) {
                const int nbase = start + ((k + STAGES) << 2);
                #pragma unroll
                for (int j = 0; j < GROUP; ++j)
                    cp16(&sbuf[w][s][j][lane], &n4[(nbase + j) * D4 + lane]);
            }
            CP_COMMIT();  // one commit per iter (possibly empty) keeps wait positional

            s = (s == STAGES - 1) ? 0 : s + 1;
        }
        CP_WAIT0();
        i = start + (ngroups << 2);
    }

    // scalar tail (also the whole range when ngroups < STAGES)
    for (; i < end; ++i) {
        const int b = load_batch(nb, i, is64);
        if (b != cur_b) {
            flush_seg(out, cur_b, lane, acc);
            acc = make_float4(0.f, 0.f, 0.f, 0.f);
            cur_b = b;
            gv = __ldg(&g4[b * D4 + lane]);
        }
        const float4 nv = __ldcs(&n4[i * D4 + lane]);
        float d = dot4(nv, gv);
        #pragma unroll
        for (int o = 16; o > 0; o >>= 1)
            d += __shfl_xor_sync(0xffffffffu, d, o);
        acc_add(acc, sigmoidf_(d), nv);
    }

    flush_seg(out, cur_b, lane, acc);
}

extern "C" void kernel_launch(void* const* d_in, const int* in_sizes, int n_in,
                              void* d_out, int out_size) {
    const float4* n4 = (const float4*)d_in[0];   // n_embedding [N,128] f32
    const float4* g4 = (const float4*)d_in[1];   // g_embedding [G,128] f32
    const void*   nb = d_in[2];                  // n_batch [N] int32 or int64
    float* out = (float*)d_out;                  // [G,128] f32

    const int N = in_sizes[0] / D;

    const int n4cnt = out_size / 4;              // out_size divisible by D=128
    init_kernel<<<(n4cnt + 255) / 256, 256>>>((float4*)out, n4cnt, (const int*)nb, N);

    int sms = 148;
    cudaDeviceGetAttribute(&sms, cudaDevAttrMultiProcessorCount, 0);

    // balanced persistent grid: every warp gets one contiguous span
    const int blocks      = sms * MIN_BLOCKS;
    const int total_warps = blocks * WARPS_PER_BLOCK;
    int span = (N + total_warps - 1) / total_warps;
    span = (span + GROUP - 1) & ~(GROUP - 1);    // multiple of 4

    n2g_attention_kernel<<<blocks, THREADS>>>(n4, g4, nb, out, N, span);
}